// round 10
// baseline (speedup 1.0000x reference)
#include <cuda_runtime.h>
#include <cuda_bf16.h>
#include <cstdint>

// ---------------------------------------------------------------------------
// GCN 2-layer forward. N=500000, E=16e6.
// CSR + pull-mode aggregation: float atomics eliminated.
//   deg[d]   = in-degree (int atomics)
//   row[]    = exclusive prefix of deg (single-block scan); cur[] = cursors
//   csrc[]   = CSR fill: src ids grouped by dst (int atomic cursor)
//   g_x4[i]  = dinv_i * (x_i, 0)                       [float4]
//   pull1:   a1[i] = g_x4[i] + sum_{s in row(i)} g_x4[s]   (warp/node, shfl)
//   node2:   h = relu((dinv_i*a1) @ W1 + b1); g_hw2[i] = dinv_i*(h @ W2)
//   pull2:   acc = g_hw2[i] + sum g_hw2[s]; out = log_softmax(dinv_i*acc + b2)
// ---------------------------------------------------------------------------

#define NMAX 500000
#define EMAX 16000000
#define F1   16
#define F2   7
#define F2P  8

__device__ __align__(16) int   g_deg [NMAX];
__device__ __align__(16) int   g_row [NMAX + 1];
__device__ __align__(16) int   g_cur [NMAX];
__device__ __align__(16) int   g_csrc[EMAX];
__device__ __align__(16) float g_dinv[NMAX];
__device__ __align__(16) float g_x4  [(size_t)NMAX * 4];
__device__ __align__(16) float g_a1  [(size_t)NMAX * 4];
__device__ __align__(16) float g_hw2 [(size_t)NMAX * F2P];
__device__ int g_is64;

// streaming 16B load of two int64 indices
__device__ __forceinline__ longlong2 ldcs_ll2(const long long* p) {
    longlong2 r;
    asm volatile("ld.global.cs.v2.s64 {%0, %1}, [%2];"
                 : "=l"(r.x), "=l"(r.y) : "l"(p));
    return r;
}

// ---- K-1: detect edge_index dtype -----------------------------------------
__global__ void k_detect(const void* ei, int e, int n) {
    if (blockIdx.x != 0 || threadIdx.x != 0) return;
    const long long* p = (const long long*)ei;
    int ok = 1;
    int step = e / 64;
    if (step < 1) step = 1;
    for (int k = 0; k < 64; k++) {
        long long v = p[(size_t)k * step];
        if (v < 0 || v >= n) { ok = 0; break; }
    }
    g_is64 = ok;
}

// ---- K0: zero degree ------------------------------------------------------
__global__ void k_zero_deg(int n) {
    int i = blockIdx.x * blockDim.x + threadIdx.x;
    if (i < n) g_deg[i] = 0;
}

// ---- K1: in-degree count (dst half only, 2 edges/thread) ------------------
__global__ void k_degree(const void* __restrict__ ei, int e, int n) {
    int t = blockIdx.x * blockDim.x + threadIdx.x;
    int i = t * 2;
    if (i >= e) return;
    if (g_is64) {
        const long long* dstp = (const long long*)ei + e;
        if (i + 1 < e) {
            longlong2 dv = ldcs_ll2(dstp + i);
            if (dv.x >= 0 && dv.x < n) atomicAdd(&g_deg[(int)dv.x], 1);
            if (dv.y >= 0 && dv.y < n) atomicAdd(&g_deg[(int)dv.y], 1);
        } else {
            long long dv = __ldg(dstp + i);
            if (dv >= 0 && dv < n) atomicAdd(&g_deg[(int)dv], 1);
        }
    } else {
        const int* dstp = (const int*)ei + e;
        for (int k = 0; k < 2 && i + k < e; k++) {
            int d = __ldg(dstp + i + k);
            if ((unsigned)d < (unsigned)n) atomicAdd(&g_deg[d], 1);
        }
    }
}

// ---- K2: single-block exclusive scan of degrees -> row offsets + cursors --
__global__ void k_scan(int n) {
    __shared__ int ssum[1024];
    int t = threadIdx.x;
    int chunk = (n + 1023) / 1024;
    int beg = t * chunk;
    int end = min(beg + chunk, n);
    int s = 0;
    for (int i = beg; i < end; i++) s += g_deg[i];
    ssum[t] = s;
    __syncthreads();
    // Hillis-Steele inclusive scan over 1024 partials
    for (int off = 1; off < 1024; off <<= 1) {
        int u = 0;
        if (t >= off) u = ssum[t - off];
        __syncthreads();
        if (t >= off) ssum[t] += u;
        __syncthreads();
    }
    int run = ssum[t] - s;   // exclusive prefix for this chunk
    for (int i = beg; i < end; i++) {
        g_row[i] = run;
        g_cur[i] = run;
        run += g_deg[i];
    }
    if (t == 1023) g_row[n] = ssum[1023];
}

// ---- K3: CSR fill (2 edges/thread) ----------------------------------------
__global__ void k_fill(const void* __restrict__ ei, int e, int n) {
    int t = blockIdx.x * blockDim.x + threadIdx.x;
    int i = t * 2;
    if (i >= e) return;
    if (g_is64) {
        const long long* srcp = (const long long*)ei;
        const long long* dstp = srcp + e;
        if (i + 1 < e) {
            longlong2 sv = ldcs_ll2(srcp + i);
            longlong2 dv = ldcs_ll2(dstp + i);
            if (sv.x >= 0 && sv.x < n && dv.x >= 0 && dv.x < n) {
                int pos = atomicAdd(&g_cur[(int)dv.x], 1);
                g_csrc[pos] = (int)sv.x;
            }
            if (sv.y >= 0 && sv.y < n && dv.y >= 0 && dv.y < n) {
                int pos = atomicAdd(&g_cur[(int)dv.y], 1);
                g_csrc[pos] = (int)sv.y;
            }
        } else {
            long long sv = __ldg(srcp + i), dv = __ldg(dstp + i);
            if (sv >= 0 && sv < n && dv >= 0 && dv < n) {
                int pos = atomicAdd(&g_cur[(int)dv], 1);
                g_csrc[pos] = (int)sv;
            }
        }
    } else {
        const int* srcp = (const int*)ei;
        const int* dstp = srcp + e;
        for (int k = 0; k < 2 && i + k < e; k++) {
            int s = __ldg(srcp + i + k), d = __ldg(dstp + i + k);
            if ((unsigned)s < (unsigned)n && (unsigned)d < (unsigned)n) {
                int pos = atomicAdd(&g_cur[d], 1);
                g_csrc[pos] = s;
            }
        }
    }
}

// ---- K4: dinv, scaled x (padded float4) -----------------------------------
__global__ void k_node1(const float* __restrict__ x, int n) {
    int i = blockIdx.x * blockDim.x + threadIdx.x;
    if (i >= n) return;
    float di = rsqrtf((float)(g_deg[i] + 1));
    g_dinv[i] = di;
    float4 v = make_float4(di * __ldg(&x[3*i+0]),
                           di * __ldg(&x[3*i+1]),
                           di * __ldg(&x[3*i+2]), 0.0f);
    ((float4*)g_x4)[i] = v;
}

// ---- K5: layer-1 pull aggregation (one warp per node) ---------------------
__global__ void k_pull1(int n) {
    int gt   = blockIdx.x * blockDim.x + threadIdx.x;
    int node = gt >> 5;
    int lane = gt & 31;
    if (node >= n) return;
    int beg = __ldg(&g_row[node]);
    int end = __ldg(&g_row[node + 1]);
    float ax = 0.0f, ay = 0.0f, az = 0.0f;
    if (lane == 0) {                      // self-loop term
        float4 v = ((const float4*)g_x4)[node];
        ax = v.x; ay = v.y; az = v.z;
    }
    for (int j = beg + lane; j < end; j += 32) {
        int s = __ldg(&g_csrc[j]);        // coalesced
        float4 v = __ldg(&((const float4*)g_x4)[s]);
        ax += v.x; ay += v.y; az += v.z;
    }
    #pragma unroll
    for (int off = 16; off > 0; off >>= 1) {
        ax += __shfl_xor_sync(0xFFFFFFFF, ax, off);
        ay += __shfl_xor_sync(0xFFFFFFFF, ay, off);
        az += __shfl_xor_sync(0xFFFFFFFF, az, off);
    }
    if (lane == 0)
        ((float4*)g_a1)[node] = make_float4(ax, ay, az, 0.0f);
}

// ---- K6: finish layer 1 (3->16 GEMM, ReLU), build scaled hW2 --------------
__global__ void k_node2(const float* __restrict__ W1,
                        const float* __restrict__ b1,
                        const float* __restrict__ W2, int n) {
    int i = blockIdx.x * blockDim.x + threadIdx.x;
    if (i >= n) return;
    float di = g_dinv[i];
    float4 a = ((const float4*)g_a1)[i];
    float a0 = di * a.x, a1v = di * a.y, a2 = di * a.z;
    float h[F1];
    #pragma unroll
    for (int j = 0; j < F1; j++)
        h[j] = fmaxf(a0 * __ldg(&W1[j]) + a1v * __ldg(&W1[F1 + j])
                   + a2 * __ldg(&W1[2*F1 + j]) + __ldg(&b1[j]), 0.0f);
    size_t ob = (size_t)i * F2P;
    float v[F2P];
    #pragma unroll
    for (int j = 0; j < F2; j++) {
        float acc = 0.0f;
        #pragma unroll
        for (int k = 0; k < F1; k++)
            acc += h[k] * __ldg(&W2[k * F2 + j]);
        v[j] = di * acc;
    }
    v[F2] = 0.0f;
    ((float4*)(g_hw2 + ob))[0] = make_float4(v[0], v[1], v[2], v[3]);
    ((float4*)(g_hw2 + ob))[1] = make_float4(v[4], v[5], v[6], v[7]);
}

// ---- K7: layer-2 pull aggregation + log_softmax (one warp per node) -------
__global__ void k_pull2(const float* __restrict__ b2,
                        float* __restrict__ out, int n) {
    int gt   = blockIdx.x * blockDim.x + threadIdx.x;
    int node = gt >> 5;
    int lane = gt & 31;
    if (node >= n) return;
    int beg = __ldg(&g_row[node]);
    int end = __ldg(&g_row[node + 1]);
    float acc[F2P];
    #pragma unroll
    for (int j = 0; j < F2P; j++) acc[j] = 0.0f;
    if (lane == 0) {                      // self-loop term
        const float4* sp = (const float4*)(g_hw2 + (size_t)node * F2P);
        float4 p0 = sp[0], p1 = sp[1];
        acc[0]=p0.x; acc[1]=p0.y; acc[2]=p0.z; acc[3]=p0.w;
        acc[4]=p1.x; acc[5]=p1.y; acc[6]=p1.z; acc[7]=p1.w;
    }
    for (int j = beg + lane; j < end; j += 32) {
        int s = __ldg(&g_csrc[j]);
        const float4* sp = (const float4*)(g_hw2 + (size_t)s * F2P);
        float4 p0 = __ldg(&sp[0]), p1 = __ldg(&sp[1]);
        acc[0]+=p0.x; acc[1]+=p0.y; acc[2]+=p0.z; acc[3]+=p0.w;
        acc[4]+=p1.x; acc[5]+=p1.y; acc[6]+=p1.z; acc[7]+=p1.w;
    }
    #pragma unroll
    for (int j = 0; j < F2; j++) {        // only 7 channels matter
        #pragma unroll
        for (int off = 16; off > 0; off >>= 1)
            acc[j] += __shfl_xor_sync(0xFFFFFFFF, acc[j], off);
    }
    if (lane == 0) {
        float di = g_dinv[node];
        float v[F2];
        float m = -1e30f;
        #pragma unroll
        for (int j = 0; j < F2; j++) {
            v[j] = di * acc[j] + __ldg(&b2[j]);
            m = fmaxf(m, v[j]);
        }
        float sum = 0.0f;
        #pragma unroll
        for (int j = 0; j < F2; j++) sum += __expf(v[j] - m);
        float lse = m + __logf(sum);
        #pragma unroll
        for (int j = 0; j < F2; j++) out[(size_t)node * F2 + j] = v[j] - lse;
    }
}

// ---------------------------------------------------------------------------
extern "C" void kernel_launch(void* const* d_in, const int* in_sizes, int n_in,
                              void* d_out, int out_size) {
    const float* x  = (const float*)d_in[0];
    const void*  ei = d_in[1];                 // [2, E] int64 OR int32 (detected)
    const float* W1 = (const float*)d_in[2];
    const float* b1 = (const float*)d_in[3];
    const float* W2 = (const float*)d_in[4];
    const float* b2 = (const float*)d_in[5];
    float*       out = (float*)d_out;

    const int n = in_sizes[0] / 3;
    int e = in_sizes[1] / 2;
    if (e > EMAX) e = EMAX;

    const int BT = 256;
    const int nb_n  = (n + BT - 1) / BT;
    const int nb_e2 = (e / 2 + BT) / BT;          // 2 edges per thread
    const int nb_w  = ((size_t)n * 32 + BT - 1) / BT;  // 1 warp per node

    k_detect  <<<1, 32>>>(ei, e, n);
    k_zero_deg<<<nb_n,  BT>>>(n);
    k_degree  <<<nb_e2, BT>>>(ei, e, n);
    k_scan    <<<1, 1024>>>(n);
    k_fill    <<<nb_e2, BT>>>(ei, e, n);
    k_node1   <<<nb_n,  BT>>>(x, n);
    k_pull1   <<<nb_w,  BT>>>(n);
    k_node2   <<<nb_n,  BT>>>(W1, b1, W2, n);
    k_pull2   <<<nb_w,  BT>>>(b2, out, n);
}

// round 12
// speedup vs baseline: 2.8573x; 2.8573x over previous
#include <cuda_runtime.h>
#include <cuda_bf16.h>
#include <cstdint>

// ---------------------------------------------------------------------------
// GCN 2-layer forward. N=500000, E=16e6.
// HYPOTHESIS under test (from crash-ledger analysis): edge_index is staged as
// INT32. The int32 path is the hot path and is vectorized (int4 = 4 edges per
// load); an int64 guarded scalar path is kept as fallback via runtime detect.
//
// Rank-3 trick + norm folding (push mode, red.v4 atomics):
//   g_x4[i]  = dinv_i * (x_i, 0)                 [float4]
//   a1[d]   += g_x4[s]; init a1[i] = g_x4[i]     (self loop)
//   h[i]     = relu( (dinv_i * a1[i]) @ W1 + b1 )
//   g_hw2[i] = dinv_i * (h[i] @ W2)              [8 floats, 7 used]
//   acc2[d] += g_hw2[s]; init acc2[i] = g_hw2[i]
//   out      = log_softmax(dinv_i*acc2[i] + b2)
// ---------------------------------------------------------------------------

#define NMAX 500000
#define F1   16
#define F2   7
#define F2P  8

__device__ __align__(16) int   g_deg [NMAX];
__device__ __align__(16) float g_dinv[NMAX];
__device__ __align__(16) float g_x4  [(size_t)NMAX * 4];
__device__ __align__(16) float g_a1  [(size_t)NMAX * 4];
__device__ __align__(16) float g_hw2 [(size_t)NMAX * F2P];
__device__ __align__(16) float g_acc2[(size_t)NMAX * F2P];
__device__ int g_is64;

__device__ __forceinline__ void red_add_v4(float* addr, float4 v) {
    asm volatile("red.global.add.v4.f32 [%0], {%1, %2, %3, %4};"
                 :: "l"(addr), "f"(v.x), "f"(v.y), "f"(v.z), "f"(v.w)
                 : "memory");
}

// ---- K-1: detect edge_index dtype (int64 values in range <=> is64) --------
__global__ void k_detect(const void* ei, int e, int n) {
    if (blockIdx.x != 0 || threadIdx.x != 0) return;
    const long long* p = (const long long*)ei;
    int ok = 1;
    int step = e / 64;
    if (step < 1) step = 1;
    // Sampling stays inside the int32 extent (8e bytes) so it is safe even
    // when the buffer is actually int32.
    for (int k = 0; k < 64; k++) {
        size_t idx = (size_t)k * step;
        if (idx * 8 + 8 > (size_t)e * 4 * 2) break;
        long long v = p[idx];
        if (v < 0 || v >= n) { ok = 0; break; }
    }
    g_is64 = ok;
}

// ---- K0: zero degree ------------------------------------------------------
__global__ void k_zero_deg(int n) {
    int i = blockIdx.x * blockDim.x + threadIdx.x;
    if (i < n) g_deg[i] = 0;
}

// ---- K1: in-degree count (dst half only; int32 hot path: 4 edges/thread) --
__global__ void k_degree(const void* __restrict__ ei, int e, int n) {
    int t = blockIdx.x * blockDim.x + threadIdx.x;
    if (g_is64) {
        int i = t;
        if (i >= e) return;
        long long dv = __ldg(&((const long long*)ei)[(size_t)e + i]);
        if (dv >= 0 && dv < n) atomicAdd(&g_deg[(int)dv], 1);
    } else {
        int i = t * 4;
        if (i >= e) return;
        const int* dstp = (const int*)ei + e;
        if (i + 3 < e) {
            int4 d4 = __ldg((const int4*)(dstp + i));
            if ((unsigned)d4.x < (unsigned)n) atomicAdd(&g_deg[d4.x], 1);
            if ((unsigned)d4.y < (unsigned)n) atomicAdd(&g_deg[d4.y], 1);
            if ((unsigned)d4.z < (unsigned)n) atomicAdd(&g_deg[d4.z], 1);
            if ((unsigned)d4.w < (unsigned)n) atomicAdd(&g_deg[d4.w], 1);
        } else {
            for (int k = 0; k < 4 && i + k < e; k++) {
                int d = __ldg(dstp + i + k);
                if ((unsigned)d < (unsigned)n) atomicAdd(&g_deg[d], 1);
            }
        }
    }
}

// ---- K2: dinv, scaled x (padded float4) + a1 init -------------------------
__global__ void k_node1(const float* __restrict__ x, int n) {
    int i = blockIdx.x * blockDim.x + threadIdx.x;
    if (i >= n) return;
    float di = rsqrtf((float)(g_deg[i] + 1));
    g_dinv[i] = di;
    float4 v = make_float4(di * __ldg(&x[3*i+0]),
                           di * __ldg(&x[3*i+1]),
                           di * __ldg(&x[3*i+2]), 0.0f);
    ((float4*)g_x4)[i] = v;
    ((float4*)g_a1)[i] = v;   // accumulator init = self-loop term
}

// ---- K3: layer-1 edge scatter (int32 hot path: 4 edges/thread) ------------
__global__ void k_edge1(const void* __restrict__ ei, int e, int n) {
    int t = blockIdx.x * blockDim.x + threadIdx.x;
    if (g_is64) {
        int i = t;
        if (i >= e) return;
        const long long* p = (const long long*)ei;
        long long sv = __ldg(&p[i]), dv = __ldg(&p[(size_t)e + i]);
        if (sv >= 0 && sv < n && dv >= 0 && dv < n)
            red_add_v4(g_a1 + (size_t)(int)dv * 4,
                       __ldg(&((const float4*)g_x4)[(int)sv]));
    } else {
        int i = t * 4;
        if (i >= e) return;
        const int* srcp = (const int*)ei;
        const int* dstp = srcp + e;
        if (i + 3 < e) {
            int4 s4 = __ldg((const int4*)(srcp + i));
            int4 d4 = __ldg((const int4*)(dstp + i));
            const float4* xt = (const float4*)g_x4;
            if ((unsigned)s4.x < (unsigned)n && (unsigned)d4.x < (unsigned)n)
                red_add_v4(g_a1 + (size_t)d4.x * 4, __ldg(&xt[s4.x]));
            if ((unsigned)s4.y < (unsigned)n && (unsigned)d4.y < (unsigned)n)
                red_add_v4(g_a1 + (size_t)d4.y * 4, __ldg(&xt[s4.y]));
            if ((unsigned)s4.z < (unsigned)n && (unsigned)d4.z < (unsigned)n)
                red_add_v4(g_a1 + (size_t)d4.z * 4, __ldg(&xt[s4.z]));
            if ((unsigned)s4.w < (unsigned)n && (unsigned)d4.w < (unsigned)n)
                red_add_v4(g_a1 + (size_t)d4.w * 4, __ldg(&xt[s4.w]));
        } else {
            for (int k = 0; k < 4 && i + k < e; k++) {
                int s = __ldg(srcp + i + k), d = __ldg(dstp + i + k);
                if ((unsigned)s < (unsigned)n && (unsigned)d < (unsigned)n)
                    red_add_v4(g_a1 + (size_t)d * 4,
                               __ldg(&((const float4*)g_x4)[s]));
            }
        }
    }
}

// ---- K4: finish layer 1 (3->16 GEMM, ReLU), build scaled hW2 --------------
__global__ void k_node2(const float* __restrict__ W1,
                        const float* __restrict__ b1,
                        const float* __restrict__ W2, int n) {
    int i = blockIdx.x * blockDim.x + threadIdx.x;
    if (i >= n) return;
    float di = g_dinv[i];
    float4 a = ((const float4*)g_a1)[i];
    float a0 = di * a.x, a1v = di * a.y, a2 = di * a.z;
    float h[F1];
    #pragma unroll
    for (int j = 0; j < F1; j++)
        h[j] = fmaxf(a0 * __ldg(&W1[j]) + a1v * __ldg(&W1[F1 + j])
                   + a2 * __ldg(&W1[2*F1 + j]) + __ldg(&b1[j]), 0.0f);
    size_t ob = (size_t)i * F2P;
    float v[F2P];
    #pragma unroll
    for (int j = 0; j < F2; j++) {
        float acc = 0.0f;
        #pragma unroll
        for (int k = 0; k < F1; k++)
            acc += h[k] * __ldg(&W2[k * F2 + j]);
        v[j] = di * acc;
    }
    v[F2] = 0.0f;
    float4 p0 = make_float4(v[0], v[1], v[2], v[3]);
    float4 p1 = make_float4(v[4], v[5], v[6], v[7]);
    ((float4*)(g_hw2  + ob))[0] = p0;
    ((float4*)(g_hw2  + ob))[1] = p1;
    ((float4*)(g_acc2 + ob))[0] = p0;   // accumulator init = self-loop term
    ((float4*)(g_acc2 + ob))[1] = p1;
}

// ---- K5: layer-2 edge scatter (int32 hot path: 4 edges/thread) ------------
__global__ void k_edge2(const void* __restrict__ ei, int e, int n) {
    int t = blockIdx.x * blockDim.x + threadIdx.x;
    if (g_is64) {
        int i = t;
        if (i >= e) return;
        const long long* p = (const long long*)ei;
        long long sv = __ldg(&p[i]), dv = __ldg(&p[(size_t)e + i]);
        if (sv >= 0 && sv < n && dv >= 0 && dv < n) {
            const float4* xs = (const float4*)(g_hw2 + (size_t)(int)sv * F2P);
            float* ad = g_acc2 + (size_t)(int)dv * F2P;
            red_add_v4(ad + 0, __ldg(&xs[0]));
            red_add_v4(ad + 4, __ldg(&xs[1]));
        }
    } else {
        int i = t * 4;
        if (i >= e) return;
        const int* srcp = (const int*)ei;
        const int* dstp = srcp + e;
        if (i + 3 < e) {
            int4 s4 = __ldg((const int4*)(srcp + i));
            int4 d4 = __ldg((const int4*)(dstp + i));
            int ss[4] = {s4.x, s4.y, s4.z, s4.w};
            int dd[4] = {d4.x, d4.y, d4.z, d4.w};
            #pragma unroll
            for (int k = 0; k < 4; k++) {
                if ((unsigned)ss[k] < (unsigned)n && (unsigned)dd[k] < (unsigned)n) {
                    const float4* xs = (const float4*)(g_hw2 + (size_t)ss[k] * F2P);
                    float* ad = g_acc2 + (size_t)dd[k] * F2P;
                    red_add_v4(ad + 0, __ldg(&xs[0]));
                    red_add_v4(ad + 4, __ldg(&xs[1]));
                }
            }
        } else {
            for (int k = 0; k < 4 && i + k < e; k++) {
                int s = __ldg(srcp + i + k), d = __ldg(dstp + i + k);
                if ((unsigned)s < (unsigned)n && (unsigned)d < (unsigned)n) {
                    const float4* xs = (const float4*)(g_hw2 + (size_t)s * F2P);
                    float* ad = g_acc2 + (size_t)d * F2P;
                    red_add_v4(ad + 0, __ldg(&xs[0]));
                    red_add_v4(ad + 4, __ldg(&xs[1]));
                }
            }
        }
    }
}

// ---- K6: apply dinv, +b2, log_softmax -------------------------------------
__global__ void k_out(const float* __restrict__ b2, float* __restrict__ out, int n) {
    int i = blockIdx.x * blockDim.x + threadIdx.x;
    if (i >= n) return;
    float di = g_dinv[i];
    size_t ob = (size_t)i * F2P;
    float v[F2];
    float m = -1e30f;
    #pragma unroll
    for (int j = 0; j < F2; j++) {
        v[j] = di * g_acc2[ob + j] + __ldg(&b2[j]);
        m = fmaxf(m, v[j]);
    }
    float sum = 0.0f;
    #pragma unroll
    for (int j = 0; j < F2; j++) sum += __expf(v[j] - m);
    float lse = m + __logf(sum);
    #pragma unroll
    for (int j = 0; j < F2; j++) out[(size_t)i * F2 + j] = v[j] - lse;
}

// ---------------------------------------------------------------------------
extern "C" void kernel_launch(void* const* d_in, const int* in_sizes, int n_in,
                              void* d_out, int out_size) {
    const float* x  = (const float*)d_in[0];
    const void*  ei = d_in[1];                 // [2, E] int32 (detected; int64 fallback)
    const float* W1 = (const float*)d_in[2];
    const float* b1 = (const float*)d_in[3];
    const float* W2 = (const float*)d_in[4];
    const float* b2 = (const float*)d_in[5];
    float*       out = (float*)d_out;

    const int n = in_sizes[0] / 3;
    const int e = in_sizes[1] / 2;

    const int BT = 256;
    const int nb_n = (n + BT - 1) / BT;
    const int nb_e = (e + BT - 1) / BT;   // covers both paths (int64 needs e threads)

    k_detect  <<<1, 32>>>(ei, e, n);
    k_zero_deg<<<nb_n, BT>>>(n);
    k_degree  <<<nb_e, BT>>>(ei, e, n);
    k_node1   <<<nb_n, BT>>>(x, n);
    k_edge1   <<<nb_e, BT>>>(ei, e, n);
    k_node2   <<<nb_n, BT>>>(W1, b1, W2, n);
    k_edge2   <<<nb_e, BT>>>(ei, e, n);
    k_out     <<<nb_n, BT>>>(b2, out, n);
}

// round 13
// speedup vs baseline: 2.9839x; 1.0443x over previous
#include <cuda_runtime.h>
#include <cuda_bf16.h>
#include <cstdint>

// ---------------------------------------------------------------------------
// GCN 2-layer forward. N=500000, E=16e6.  (R9-proven structure)
// Rank-3 trick + norm folding (push mode, red.v4 atomics):
//   g_x4[i]  = dinv_i * (x_i, 0)                 [float4]
//   a1[d]   += g_x4[s]; init a1[i] = g_x4[i]     (self loop)
//   h[i]     = relu( (dinv_i * a1[i]) @ W1 + b1 )
//   hw2a/b   = dinv_i * (h[i] @ W2)  split into 2 float4 arrays so the two
//              per-edge reductions hit DIFFERENT L2 lines/slices
//   acc2a/b[d] += hw2a/b[s]; init = self-loop term
//   out      = log_softmax(dinv_i*acc2 + b2)
// 2 edges/thread; int32 hot path with int2 index loads; int64 scalar fallback.
// ---------------------------------------------------------------------------

#define NMAX 500000
#define F1   16
#define F2   7

__device__ __align__(16) int   g_deg  [NMAX];
__device__ __align__(16) float g_dinv [NMAX];
__device__ __align__(16) float g_x4   [(size_t)NMAX * 4];
__device__ __align__(16) float g_a1   [(size_t)NMAX * 4];
__device__ __align__(16) float g_hw2a [(size_t)NMAX * 4];
__device__ __align__(16) float g_hw2b [(size_t)NMAX * 4];
__device__ __align__(16) float g_acc2a[(size_t)NMAX * 4];
__device__ __align__(16) float g_acc2b[(size_t)NMAX * 4];
__device__ int g_is64;

__device__ __forceinline__ void red_add_v4(float* addr, float4 v) {
    asm volatile("red.global.add.v4.f32 [%0], {%1, %2, %3, %4};"
                 :: "l"(addr), "f"(v.x), "f"(v.y), "f"(v.z), "f"(v.w)
                 : "memory");
}

// ---- K-1: detect edge_index dtype ------------------------------------------
__global__ void k_detect(const void* ei, int e, int n) {
    if (blockIdx.x != 0 || threadIdx.x != 0) return;
    const long long* p = (const long long*)ei;
    int ok = 1;
    int step = e / 64;
    if (step < 1) step = 1;
    for (int k = 0; k < 64; k++) {
        size_t idx = (size_t)k * step;
        if (idx * 8 + 8 > (size_t)e * 8) break;   // stay inside int32 extent too
        long long v = p[idx];
        if (v < 0 || v >= n) { ok = 0; break; }
    }
    g_is64 = ok;
}

// ---- K0: zero degree -------------------------------------------------------
__global__ void k_zero_deg(int n) {
    int i = blockIdx.x * blockDim.x + threadIdx.x;
    if (i < n) g_deg[i] = 0;
}

// ---- K1: in-degree count (dst half only, 2 edges/thread) -------------------
__global__ void k_degree(const void* __restrict__ ei, int e, int n) {
    int t = blockIdx.x * blockDim.x + threadIdx.x;
    int i = t * 2;
    if (i >= e) return;
    if (g_is64) {
        const long long* dstp = (const long long*)ei + e;
        for (int k = 0; k < 2 && i + k < e; k++) {
            long long dv = __ldg(dstp + i + k);
            if (dv >= 0 && dv < n) atomicAdd(&g_deg[(int)dv], 1);
        }
    } else {
        const int* dstp = (const int*)ei + e;
        if (i + 1 < e) {
            int2 d2 = __ldg((const int2*)(dstp + i));
            if ((unsigned)d2.x < (unsigned)n) atomicAdd(&g_deg[d2.x], 1);
            if ((unsigned)d2.y < (unsigned)n) atomicAdd(&g_deg[d2.y], 1);
        } else {
            int d = __ldg(dstp + i);
            if ((unsigned)d < (unsigned)n) atomicAdd(&g_deg[d], 1);
        }
    }
}

// ---- K2: dinv, scaled x (padded float4) + a1 init --------------------------
__global__ void k_node1(const float* __restrict__ x, int n) {
    int i = blockIdx.x * blockDim.x + threadIdx.x;
    if (i >= n) return;
    float di = rsqrtf((float)(g_deg[i] + 1));
    g_dinv[i] = di;
    float4 v = make_float4(di * __ldg(&x[3*i+0]),
                           di * __ldg(&x[3*i+1]),
                           di * __ldg(&x[3*i+2]), 0.0f);
    ((float4*)g_x4)[i] = v;
    ((float4*)g_a1)[i] = v;   // accumulator init = self-loop term
}

// ---- K3: layer-1 edge scatter (2 edges/thread) -----------------------------
__global__ void k_edge1(const void* __restrict__ ei, int e, int n) {
    int t = blockIdx.x * blockDim.x + threadIdx.x;
    int i = t * 2;
    if (i >= e) return;
    const float4* xt = (const float4*)g_x4;
    if (g_is64) {
        const long long* srcp = (const long long*)ei;
        const long long* dstp = srcp + e;
        for (int k = 0; k < 2 && i + k < e; k++) {
            long long sv = __ldg(srcp + i + k), dv = __ldg(dstp + i + k);
            if (sv >= 0 && sv < n && dv >= 0 && dv < n)
                red_add_v4(g_a1 + (size_t)(int)dv * 4, __ldg(&xt[(int)sv]));
        }
    } else {
        const int* srcp = (const int*)ei;
        const int* dstp = srcp + e;
        if (i + 1 < e) {
            int2 s2 = __ldg((const int2*)(srcp + i));
            int2 d2 = __ldg((const int2*)(dstp + i));
            if ((unsigned)s2.x < (unsigned)n && (unsigned)d2.x < (unsigned)n)
                red_add_v4(g_a1 + (size_t)d2.x * 4, __ldg(&xt[s2.x]));
            if ((unsigned)s2.y < (unsigned)n && (unsigned)d2.y < (unsigned)n)
                red_add_v4(g_a1 + (size_t)d2.y * 4, __ldg(&xt[s2.y]));
        } else {
            int s = __ldg(srcp + i), d = __ldg(dstp + i);
            if ((unsigned)s < (unsigned)n && (unsigned)d < (unsigned)n)
                red_add_v4(g_a1 + (size_t)d * 4, __ldg(&xt[s]));
        }
    }
}

// ---- K4: finish layer 1 (3->16 GEMM, ReLU), build split scaled hW2 ---------
__global__ void k_node2(const float* __restrict__ W1,
                        const float* __restrict__ b1,
                        const float* __restrict__ W2, int n) {
    int i = blockIdx.x * blockDim.x + threadIdx.x;
    if (i >= n) return;
    float di = g_dinv[i];
    float4 a = ((const float4*)g_a1)[i];
    float a0 = di * a.x, a1v = di * a.y, a2 = di * a.z;
    float h[F1];
    #pragma unroll
    for (int j = 0; j < F1; j++)
        h[j] = fmaxf(a0 * __ldg(&W1[j]) + a1v * __ldg(&W1[F1 + j])
                   + a2 * __ldg(&W1[2*F1 + j]) + __ldg(&b1[j]), 0.0f);
    float v[8];
    #pragma unroll
    for (int j = 0; j < F2; j++) {
        float acc = 0.0f;
        #pragma unroll
        for (int k = 0; k < F1; k++)
            acc += h[k] * __ldg(&W2[k * F2 + j]);
        v[j] = di * acc;
    }
    v[F2] = 0.0f;
    float4 p0 = make_float4(v[0], v[1], v[2], v[3]);
    float4 p1 = make_float4(v[4], v[5], v[6], v[7]);
    ((float4*)g_hw2a)[i]  = p0;
    ((float4*)g_hw2b)[i]  = p1;
    ((float4*)g_acc2a)[i] = p0;   // accumulator init = self-loop term
    ((float4*)g_acc2b)[i] = p1;
}

// ---- K5: layer-2 edge scatter (2 edges/thread, split arrays) ---------------
__global__ void k_edge2(const void* __restrict__ ei, int e, int n) {
    int t = blockIdx.x * blockDim.x + threadIdx.x;
    int i = t * 2;
    if (i >= e) return;
    const float4* ha = (const float4*)g_hw2a;
    const float4* hb = (const float4*)g_hw2b;
    if (g_is64) {
        const long long* srcp = (const long long*)ei;
        const long long* dstp = srcp + e;
        for (int k = 0; k < 2 && i + k < e; k++) {
            long long sv = __ldg(srcp + i + k), dv = __ldg(dstp + i + k);
            if (sv >= 0 && sv < n && dv >= 0 && dv < n) {
                int s = (int)sv, d = (int)dv;
                red_add_v4(g_acc2a + (size_t)d * 4, __ldg(&ha[s]));
                red_add_v4(g_acc2b + (size_t)d * 4, __ldg(&hb[s]));
            }
        }
    } else {
        const int* srcp = (const int*)ei;
        const int* dstp = srcp + e;
        if (i + 1 < e) {
            int2 s2 = __ldg((const int2*)(srcp + i));
            int2 d2 = __ldg((const int2*)(dstp + i));
            if ((unsigned)s2.x < (unsigned)n && (unsigned)d2.x < (unsigned)n) {
                red_add_v4(g_acc2a + (size_t)d2.x * 4, __ldg(&ha[s2.x]));
                red_add_v4(g_acc2b + (size_t)d2.x * 4, __ldg(&hb[s2.x]));
            }
            if ((unsigned)s2.y < (unsigned)n && (unsigned)d2.y < (unsigned)n) {
                red_add_v4(g_acc2a + (size_t)d2.y * 4, __ldg(&ha[s2.y]));
                red_add_v4(g_acc2b + (size_t)d2.y * 4, __ldg(&hb[s2.y]));
            }
        } else {
            int s = __ldg(srcp + i), d = __ldg(dstp + i);
            if ((unsigned)s < (unsigned)n && (unsigned)d < (unsigned)n) {
                red_add_v4(g_acc2a + (size_t)d * 4, __ldg(&ha[s]));
                red_add_v4(g_acc2b + (size_t)d * 4, __ldg(&hb[s]));
            }
        }
    }
}

// ---- K6: apply dinv, +b2, log_softmax --------------------------------------
__global__ void k_out(const float* __restrict__ b2, float* __restrict__ out, int n) {
    int i = blockIdx.x * blockDim.x + threadIdx.x;
    if (i >= n) return;
    float di = g_dinv[i];
    float4 pa = ((const float4*)g_acc2a)[i];
    float4 pb = ((const float4*)g_acc2b)[i];
    float v[F2];
    v[0] = pa.x; v[1] = pa.y; v[2] = pa.z; v[3] = pa.w;
    v[4] = pb.x; v[5] = pb.y; v[6] = pb.z;
    float m = -1e30f;
    #pragma unroll
    for (int j = 0; j < F2; j++) {
        v[j] = di * v[j] + __ldg(&b2[j]);
        m = fmaxf(m, v[j]);
    }
    float sum = 0.0f;
    #pragma unroll
    for (int j = 0; j < F2; j++) sum += __expf(v[j] - m);
    float lse = m + __logf(sum);
    #pragma unroll
    for (int j = 0; j < F2; j++) out[(size_t)i * F2 + j] = v[j] - lse;
}

// ---------------------------------------------------------------------------
extern "C" void kernel_launch(void* const* d_in, const int* in_sizes, int n_in,
                              void* d_out, int out_size) {
    const float* x  = (const float*)d_in[0];
    const void*  ei = d_in[1];                 // [2, E] dtype detected at runtime
    const float* W1 = (const float*)d_in[2];
    const float* b1 = (const float*)d_in[3];
    const float* W2 = (const float*)d_in[4];
    const float* b2 = (const float*)d_in[5];
    float*       out = (float*)d_out;

    const int n = in_sizes[0] / 3;
    const int e = in_sizes[1] / 2;

    const int BT = 256;
    const int nb_n  = (n + BT - 1) / BT;
    const int nb_e2 = (e / 2 + BT) / BT;   // 2 edges per thread (both paths)

    k_detect  <<<1, 32>>>(ei, e, n);
    k_zero_deg<<<nb_n,  BT>>>(n);
    k_degree  <<<nb_e2, BT>>>(ei, e, n);
    k_node1   <<<nb_n,  BT>>>(x, n);
    k_edge1   <<<nb_e2, BT>>>(ei, e, n);
    k_node2   <<<nb_n,  BT>>>(W1, b1, W2, n);
    k_edge2   <<<nb_e2, BT>>>(ei, e, n);
    k_out     <<<nb_n,  BT>>>(b2, out, n);
}

// round 14
// speedup vs baseline: 3.9005x; 1.3072x over previous
#include <cuda_runtime.h>
#include <cuda_fp16.h>
#include <cuda_bf16.h>
#include <cstdint>

// ---------------------------------------------------------------------------
// GCN 2-layer forward. N=500000, E=16e6.  (R9-proven structure)
// Rank-3 trick + norm folding (push mode):
//   g_x4[i]  = dinv_i * (x_i, 0)                 [float4]   (fp32, exact)
//   a1[d]   += g_x4[s]; init a1[i] = g_x4[i]     1 red.v4.f32 per edge
//   h[i]     = relu( (dinv_i * a1[i]) @ W1 + b1 )
//   hw2h[i]  = fp16x8( dinv_i * (h[i] @ W2) )    [7 used, pad 0]
//   acc2h[d]+= hw2h[s]  via ONE red.v4.f16x2 per edge (16B message)
//   out      = log_softmax(dinv_i*acc2h + b2)
// Layer-2 message/accumulator in fp16 halves the layer-2 L2 transactions.
// ---------------------------------------------------------------------------

#define NMAX 500000
#define F1   16
#define F2   7

__device__ __align__(16) int      g_deg  [NMAX];
__device__ __align__(16) float    g_dinv [NMAX];
__device__ __align__(16) float    g_x4   [(size_t)NMAX * 4];
__device__ __align__(16) float    g_a1   [(size_t)NMAX * 4];
__device__ __align__(16) __half   g_hw2h [(size_t)NMAX * 8];   // fp16 messages
__device__ __align__(16) __half   g_acc2h[(size_t)NMAX * 8];   // fp16 accumulator
__device__ int g_is64;

__device__ __forceinline__ void red_add_v4(float* addr, float4 v) {
    asm volatile("red.global.add.v4.f32 [%0], {%1, %2, %3, %4};"
                 :: "l"(addr), "f"(v.x), "f"(v.y), "f"(v.z), "f"(v.w)
                 : "memory");
}

// one 16B fp16 vector reduction: 8 halves in 4 f16x2 words
__device__ __forceinline__ void red_add_v4_f16x2(void* addr, uint4 m) {
    asm volatile("red.global.add.noftz.v4.f16x2 [%0], {%1, %2, %3, %4};"
                 :: "l"(addr), "r"(m.x), "r"(m.y), "r"(m.z), "r"(m.w)
                 : "memory");
}

// streaming 16B load of two int64 indices
__device__ __forceinline__ longlong2 ldcs_ll2(const long long* p) {
    longlong2 r;
    asm volatile("ld.global.cs.v2.s64 {%0, %1}, [%2];"
                 : "=l"(r.x), "=l"(r.y) : "l"(p));
    return r;
}

// ---- K-1: detect edge_index dtype ------------------------------------------
__global__ void k_detect(const void* ei, int e, int n) {
    if (blockIdx.x != 0 || threadIdx.x != 0) return;
    const long long* p = (const long long*)ei;
    int ok = 1;
    int step = e / 64;
    if (step < 1) step = 1;
    for (int k = 0; k < 64; k++) {
        size_t idx = (size_t)k * step;
        if (idx * 8 + 8 > (size_t)e * 8) break;   // stay inside int32 extent too
        long long v = p[idx];
        if (v < 0 || v >= n) { ok = 0; break; }
    }
    g_is64 = ok;
}

// ---- K0: zero degree -------------------------------------------------------
__global__ void k_zero_deg(int n) {
    int i = blockIdx.x * blockDim.x + threadIdx.x;
    if (i < n) g_deg[i] = 0;
}

// ---- K1: in-degree count (dst half only, 2 edges/thread) -------------------
__global__ void k_degree(const void* __restrict__ ei, int e, int n) {
    int t = blockIdx.x * blockDim.x + threadIdx.x;
    int i = t * 2;
    if (i >= e) return;
    if (g_is64) {
        const long long* dstp = (const long long*)ei + e;
        if (i + 1 < e) {
            longlong2 dv = ldcs_ll2(dstp + i);
            if (dv.x >= 0 && dv.x < n) atomicAdd(&g_deg[(int)dv.x], 1);
            if (dv.y >= 0 && dv.y < n) atomicAdd(&g_deg[(int)dv.y], 1);
        } else {
            long long dv = __ldg(dstp + i);
            if (dv >= 0 && dv < n) atomicAdd(&g_deg[(int)dv], 1);
        }
    } else {
        const int* dstp = (const int*)ei + e;
        for (int k = 0; k < 2 && i + k < e; k++) {
            int d = __ldg(dstp + i + k);
            if ((unsigned)d < (unsigned)n) atomicAdd(&g_deg[d], 1);
        }
    }
}

// ---- K2: dinv, scaled x (padded float4) + a1 init --------------------------
__global__ void k_node1(const float* __restrict__ x, int n) {
    int i = blockIdx.x * blockDim.x + threadIdx.x;
    if (i >= n) return;
    float di = rsqrtf((float)(g_deg[i] + 1));
    g_dinv[i] = di;
    float4 v = make_float4(di * __ldg(&x[3*i+0]),
                           di * __ldg(&x[3*i+1]),
                           di * __ldg(&x[3*i+2]), 0.0f);
    ((float4*)g_x4)[i] = v;
    ((float4*)g_a1)[i] = v;   // accumulator init = self-loop term
}

// ---- K3: layer-1 edge scatter (2 edges/thread, fp32 exact) -----------------
__global__ void k_edge1(const void* __restrict__ ei, int e, int n) {
    int t = blockIdx.x * blockDim.x + threadIdx.x;
    int i = t * 2;
    if (i >= e) return;
    const float4* xt = (const float4*)g_x4;
    if (g_is64) {
        const long long* srcp = (const long long*)ei;
        const long long* dstp = srcp + e;
        if (i + 1 < e) {
            longlong2 sv = ldcs_ll2(srcp + i);
            longlong2 dv = ldcs_ll2(dstp + i);
            bool ok0 = (sv.x >= 0 && sv.x < n && dv.x >= 0 && dv.x < n);
            bool ok1 = (sv.y >= 0 && sv.y < n && dv.y >= 0 && dv.y < n);
            if (ok0) red_add_v4(g_a1 + (size_t)(int)dv.x * 4, __ldg(&xt[(int)sv.x]));
            if (ok1) red_add_v4(g_a1 + (size_t)(int)dv.y * 4, __ldg(&xt[(int)sv.y]));
        } else {
            long long sv = __ldg(srcp + i), dv = __ldg(dstp + i);
            if (sv >= 0 && sv < n && dv >= 0 && dv < n)
                red_add_v4(g_a1 + (size_t)(int)dv * 4, __ldg(&xt[(int)sv]));
        }
    } else {
        const int* srcp = (const int*)ei;
        const int* dstp = srcp + e;
        for (int k = 0; k < 2 && i + k < e; k++) {
            int s = __ldg(srcp + i + k), d = __ldg(dstp + i + k);
            if ((unsigned)s < (unsigned)n && (unsigned)d < (unsigned)n)
                red_add_v4(g_a1 + (size_t)d * 4, __ldg(&xt[s]));
        }
    }
}

// ---- K4: finish layer 1, build fp16-packed scaled hW2 ----------------------
__global__ void k_node2(const float* __restrict__ W1,
                        const float* __restrict__ b1,
                        const float* __restrict__ W2, int n) {
    int i = blockIdx.x * blockDim.x + threadIdx.x;
    if (i >= n) return;
    float di = g_dinv[i];
    float4 a = ((const float4*)g_a1)[i];
    float a0 = di * a.x, a1v = di * a.y, a2 = di * a.z;
    float h[F1];
    #pragma unroll
    for (int j = 0; j < F1; j++)
        h[j] = fmaxf(a0 * __ldg(&W1[j]) + a1v * __ldg(&W1[F1 + j])
                   + a2 * __ldg(&W1[2*F1 + j]) + __ldg(&b1[j]), 0.0f);
    float v[8];
    #pragma unroll
    for (int j = 0; j < F2; j++) {
        float acc = 0.0f;
        #pragma unroll
        for (int k = 0; k < F1; k++)
            acc += h[k] * __ldg(&W2[k * F2 + j]);
        v[j] = di * acc;
    }
    v[F2] = 0.0f;
    __half2 p0 = __floats2half2_rn(v[0], v[1]);
    __half2 p1 = __floats2half2_rn(v[2], v[3]);
    __half2 p2 = __floats2half2_rn(v[4], v[5]);
    __half2 p3 = __floats2half2_rn(v[6], v[7]);
    uint4 m;
    m.x = *(uint32_t*)&p0; m.y = *(uint32_t*)&p1;
    m.z = *(uint32_t*)&p2; m.w = *(uint32_t*)&p3;
    ((uint4*)g_hw2h)[i]  = m;
    ((uint4*)g_acc2h)[i] = m;   // accumulator init = self-loop term
}

// ---- K5: layer-2 edge scatter — ONE red.v4.f16x2 per edge ------------------
__global__ void k_edge2(const void* __restrict__ ei, int e, int n) {
    int t = blockIdx.x * blockDim.x + threadIdx.x;
    int i = t * 2;
    if (i >= e) return;
    const uint4* ht = (const uint4*)g_hw2h;
    uint4*       at = (uint4*)g_acc2h;
    if (g_is64) {
        const long long* srcp = (const long long*)ei;
        const long long* dstp = srcp + e;
        if (i + 1 < e) {
            longlong2 sv = ldcs_ll2(srcp + i);
            longlong2 dv = ldcs_ll2(dstp + i);
            if (sv.x >= 0 && sv.x < n && dv.x >= 0 && dv.x < n)
                red_add_v4_f16x2(at + (int)dv.x, __ldg(&ht[(int)sv.x]));
            if (sv.y >= 0 && sv.y < n && dv.y >= 0 && dv.y < n)
                red_add_v4_f16x2(at + (int)dv.y, __ldg(&ht[(int)sv.y]));
        } else {
            long long sv = __ldg(srcp + i), dv = __ldg(dstp + i);
            if (sv >= 0 && sv < n && dv >= 0 && dv < n)
                red_add_v4_f16x2(at + (int)dv, __ldg(&ht[(int)sv]));
        }
    } else {
        const int* srcp = (const int*)ei;
        const int* dstp = srcp + e;
        for (int k = 0; k < 2 && i + k < e; k++) {
            int s = __ldg(srcp + i + k), d = __ldg(dstp + i + k);
            if ((unsigned)s < (unsigned)n && (unsigned)d < (unsigned)n)
                red_add_v4_f16x2(at + d, __ldg(&ht[s]));
        }
    }
}

// ---- K6: unpack fp16 acc, apply dinv, +b2, log_softmax ---------------------
__global__ void k_out(const float* __restrict__ b2, float* __restrict__ out, int n) {
    int i = blockIdx.x * blockDim.x + threadIdx.x;
    if (i >= n) return;
    float di = g_dinv[i];
    uint4 m = ((const uint4*)g_acc2h)[i];
    __half2 h0 = *(__half2*)&m.x, h1 = *(__half2*)&m.y;
    __half2 h2 = *(__half2*)&m.z, h3 = *(__half2*)&m.w;
    float2 f0 = __half22float2(h0), f1 = __half22float2(h1);
    float2 f2 = __half22float2(h2), f3 = __half22float2(h3);
    float v[F2] = { f0.x, f0.y, f1.x, f1.y, f2.x, f2.y, f3.x };
    float mx = -1e30f;
    #pragma unroll
    for (int j = 0; j < F2; j++) {
        v[j] = di * v[j] + __ldg(&b2[j]);
        mx = fmaxf(mx, v[j]);
    }
    float sum = 0.0f;
    #pragma unroll
    for (int j = 0; j < F2; j++) sum += __expf(v[j] - mx);
    float lse = mx + __logf(sum);
    #pragma unroll
    for (int j = 0; j < F2; j++) out[(size_t)i * F2 + j] = v[j] - lse;
}

// ---------------------------------------------------------------------------
extern "C" void kernel_launch(void* const* d_in, const int* in_sizes, int n_in,
                              void* d_out, int out_size) {
    const float* x  = (const float*)d_in[0];
    const void*  ei = d_in[1];                 // [2, E] dtype detected at runtime
    const float* W1 = (const float*)d_in[2];
    const float* b1 = (const float*)d_in[3];
    const float* W2 = (const float*)d_in[4];
    const float* b2 = (const float*)d_in[5];
    float*       out = (float*)d_out;

    const int n = in_sizes[0] / 3;
    const int e = in_sizes[1] / 2;

    const int BT = 256;
    const int nb_n  = (n + BT - 1) / BT;
    const int nb_e2 = (e / 2 + BT) / BT;   // 2 edges per thread

    k_detect  <<<1, 32>>>(ei, e, n);
    k_zero_deg<<<nb_n,  BT>>>(n);
    k_degree  <<<nb_e2, BT>>>(ei, e, n);
    k_node1   <<<nb_n,  BT>>>(x, n);
    k_edge1   <<<nb_e2, BT>>>(ei, e, n);
    k_node2   <<<nb_n,  BT>>>(W1, b1, W2, n);
    k_edge2   <<<nb_e2, BT>>>(ei, e, n);
    k_out     <<<nb_n,  BT>>>(b2, out, n);
}

// round 15
// speedup vs baseline: 3.9835x; 1.0213x over previous
#include <cuda_runtime.h>
#include <cuda_fp16.h>
#include <cuda_bf16.h>
#include <cstdint>

// ---------------------------------------------------------------------------
// GCN 2-layer forward. N=500000, E=16e6.
// Both aggregation layers use fp16 packed messages + hardware fp16 reductions:
//   g_x4h[i]  = fp16x4( dinv_i * (x_i, 0) )      8B message
//   a1h[d]   += g_x4h[s]  via ONE red.v2.f16x2 (2 lanes) per edge
//   h[i]      = relu( (dinv_i * a1h[i]) @ W1 + b1 )
//   hw2h[i]   = fp16x8( dinv_i * (h[i] @ W2) )   16B message (7 used)
//   acc2h[d] += hw2h[s]  via ONE red.v4.f16x2 (4 lanes) per edge
//   out       = log_softmax(dinv_i*acc2h + b2)
// Per-edge red lanes: 1 (deg) + 2 + 4 = 7 (was 9 in R14).
// ---------------------------------------------------------------------------

#define NMAX 500000
#define F1   16
#define F2   7

__device__ __align__(16) int      g_deg  [NMAX];
__device__ __align__(16) float    g_dinv [NMAX];
__device__ __align__(16) __half   g_x4h  [(size_t)NMAX * 4];   // fp16 L1 messages
__device__ __align__(16) __half   g_a1h  [(size_t)NMAX * 4];   // fp16 L1 accumulator
__device__ __align__(16) __half   g_hw2h [(size_t)NMAX * 8];   // fp16 L2 messages
__device__ __align__(16) __half   g_acc2h[(size_t)NMAX * 8];   // fp16 L2 accumulator
__device__ int g_is64;

// 8B fp16 vector reduction: 4 halves in 2 f16x2 words
__device__ __forceinline__ void red_add_v2_f16x2(void* addr, uint2 m) {
    asm volatile("red.global.add.noftz.v2.f16x2 [%0], {%1, %2};"
                 :: "l"(addr), "r"(m.x), "r"(m.y)
                 : "memory");
}

// 16B fp16 vector reduction: 8 halves in 4 f16x2 words
__device__ __forceinline__ void red_add_v4_f16x2(void* addr, uint4 m) {
    asm volatile("red.global.add.noftz.v4.f16x2 [%0], {%1, %2, %3, %4};"
                 :: "l"(addr), "r"(m.x), "r"(m.y), "r"(m.z), "r"(m.w)
                 : "memory");
}

// streaming 16B load of two int64 indices
__device__ __forceinline__ longlong2 ldcs_ll2(const long long* p) {
    longlong2 r;
    asm volatile("ld.global.cs.v2.s64 {%0, %1}, [%2];"
                 : "=l"(r.x), "=l"(r.y) : "l"(p));
    return r;
}

// ---- K-1: detect edge_index dtype ------------------------------------------
__global__ void k_detect(const void* ei, int e, int n) {
    if (blockIdx.x != 0 || threadIdx.x != 0) return;
    const long long* p = (const long long*)ei;
    int ok = 1;
    int step = e / 64;
    if (step < 1) step = 1;
    for (int k = 0; k < 64; k++) {
        size_t idx = (size_t)k * step;
        if (idx * 8 + 8 > (size_t)e * 8) break;
        long long v = p[idx];
        if (v < 0 || v >= n) { ok = 0; break; }
    }
    g_is64 = ok;
}

// ---- K0: zero degree -------------------------------------------------------
__global__ void k_zero_deg(int n) {
    int i = blockIdx.x * blockDim.x + threadIdx.x;
    if (i < n) g_deg[i] = 0;
}

// ---- K1: in-degree count (dst half only, 2 edges/thread) -------------------
__global__ void k_degree(const void* __restrict__ ei, int e, int n) {
    int t = blockIdx.x * blockDim.x + threadIdx.x;
    int i = t * 2;
    if (i >= e) return;
    if (g_is64) {
        const long long* dstp = (const long long*)ei + e;
        if (i + 1 < e) {
            longlong2 dv = ldcs_ll2(dstp + i);
            if (dv.x >= 0 && dv.x < n) atomicAdd(&g_deg[(int)dv.x], 1);
            if (dv.y >= 0 && dv.y < n) atomicAdd(&g_deg[(int)dv.y], 1);
        } else {
            long long dv = __ldg(dstp + i);
            if (dv >= 0 && dv < n) atomicAdd(&g_deg[(int)dv], 1);
        }
    } else {
        const int* dstp = (const int*)ei + e;
        for (int k = 0; k < 2 && i + k < e; k++) {
            int d = __ldg(dstp + i + k);
            if ((unsigned)d < (unsigned)n) atomicAdd(&g_deg[d], 1);
        }
    }
}

// ---- K2: dinv, fp16-packed scaled x + a1 init ------------------------------
__global__ void k_node1(const float* __restrict__ x, int n) {
    int i = blockIdx.x * blockDim.x + threadIdx.x;
    if (i >= n) return;
    float di = rsqrtf((float)(g_deg[i] + 1));
    g_dinv[i] = di;
    __half2 p0 = __floats2half2_rn(di * __ldg(&x[3*i+0]), di * __ldg(&x[3*i+1]));
    __half2 p1 = __floats2half2_rn(di * __ldg(&x[3*i+2]), 0.0f);
    uint2 m;
    m.x = *(uint32_t*)&p0;
    m.y = *(uint32_t*)&p1;
    ((uint2*)g_x4h)[i] = m;
    ((uint2*)g_a1h)[i] = m;   // accumulator init = self-loop term
}

// ---- K3: layer-1 edge scatter — ONE red.v2.f16x2 per edge ------------------
__global__ void k_edge1(const void* __restrict__ ei, int e, int n) {
    int t = blockIdx.x * blockDim.x + threadIdx.x;
    int i = t * 2;
    if (i >= e) return;
    const uint2* xt = (const uint2*)g_x4h;
    uint2*       at = (uint2*)g_a1h;
    if (g_is64) {
        const long long* srcp = (const long long*)ei;
        const long long* dstp = srcp + e;
        if (i + 1 < e) {
            longlong2 sv = ldcs_ll2(srcp + i);
            longlong2 dv = ldcs_ll2(dstp + i);
            if (sv.x >= 0 && sv.x < n && dv.x >= 0 && dv.x < n)
                red_add_v2_f16x2(at + (int)dv.x, __ldg(&xt[(int)sv.x]));
            if (sv.y >= 0 && sv.y < n && dv.y >= 0 && dv.y < n)
                red_add_v2_f16x2(at + (int)dv.y, __ldg(&xt[(int)sv.y]));
        } else {
            long long sv = __ldg(srcp + i), dv = __ldg(dstp + i);
            if (sv >= 0 && sv < n && dv >= 0 && dv < n)
                red_add_v2_f16x2(at + (int)dv, __ldg(&xt[(int)sv]));
        }
    } else {
        const int* srcp = (const int*)ei;
        const int* dstp = srcp + e;
        for (int k = 0; k < 2 && i + k < e; k++) {
            int s = __ldg(srcp + i + k), d = __ldg(dstp + i + k);
            if ((unsigned)s < (unsigned)n && (unsigned)d < (unsigned)n)
                red_add_v2_f16x2(at + d, __ldg(&xt[s]));
        }
    }
}

// ---- K4: finish layer 1, build fp16-packed scaled hW2 ----------------------
__global__ void k_node2(const float* __restrict__ W1,
                        const float* __restrict__ b1,
                        const float* __restrict__ W2, int n) {
    int i = blockIdx.x * blockDim.x + threadIdx.x;
    if (i >= n) return;
    float di = g_dinv[i];
    uint2 am = ((const uint2*)g_a1h)[i];
    __half2 a01 = *(__half2*)&am.x, a23 = *(__half2*)&am.y;
    float2 f01 = __half22float2(a01), f23 = __half22float2(a23);
    float a0 = di * f01.x, a1v = di * f01.y, a2 = di * f23.x;
    float h[F1];
    #pragma unroll
    for (int j = 0; j < F1; j++)
        h[j] = fmaxf(a0 * __ldg(&W1[j]) + a1v * __ldg(&W1[F1 + j])
                   + a2 * __ldg(&W1[2*F1 + j]) + __ldg(&b1[j]), 0.0f);
    float v[8];
    #pragma unroll
    for (int j = 0; j < F2; j++) {
        float acc = 0.0f;
        #pragma unroll
        for (int k = 0; k < F1; k++)
            acc += h[k] * __ldg(&W2[k * F2 + j]);
        v[j] = di * acc;
    }
    v[F2] = 0.0f;
    __half2 p0 = __floats2half2_rn(v[0], v[1]);
    __half2 p1 = __floats2half2_rn(v[2], v[3]);
    __half2 p2 = __floats2half2_rn(v[4], v[5]);
    __half2 p3 = __floats2half2_rn(v[6], v[7]);
    uint4 m;
    m.x = *(uint32_t*)&p0; m.y = *(uint32_t*)&p1;
    m.z = *(uint32_t*)&p2; m.w = *(uint32_t*)&p3;
    ((uint4*)g_hw2h)[i]  = m;
    ((uint4*)g_acc2h)[i] = m;   // accumulator init = self-loop term
}

// ---- K5: layer-2 edge scatter — ONE red.v4.f16x2 per edge ------------------
__global__ void k_edge2(const void* __restrict__ ei, int e, int n) {
    int t = blockIdx.x * blockDim.x + threadIdx.x;
    int i = t * 2;
    if (i >= e) return;
    const uint4* ht = (const uint4*)g_hw2h;
    uint4*       at = (uint4*)g_acc2h;
    if (g_is64) {
        const long long* srcp = (const long long*)ei;
        const long long* dstp = srcp + e;
        if (i + 1 < e) {
            longlong2 sv = ldcs_ll2(srcp + i);
            longlong2 dv = ldcs_ll2(dstp + i);
            if (sv.x >= 0 && sv.x < n && dv.x >= 0 && dv.x < n)
                red_add_v4_f16x2(at + (int)dv.x, __ldg(&ht[(int)sv.x]));
            if (sv.y >= 0 && sv.y < n && dv.y >= 0 && dv.y < n)
                red_add_v4_f16x2(at + (int)dv.y, __ldg(&ht[(int)sv.y]));
        } else {
            long long sv = __ldg(srcp + i), dv = __ldg(dstp + i);
            if (sv >= 0 && sv < n && dv >= 0 && dv < n)
                red_add_v4_f16x2(at + (int)dv, __ldg(&ht[(int)sv]));
        }
    } else {
        const int* srcp = (const int*)ei;
        const int* dstp = srcp + e;
        for (int k = 0; k < 2 && i + k < e; k++) {
            int s = __ldg(srcp + i + k), d = __ldg(dstp + i + k);
            if ((unsigned)s < (unsigned)n && (unsigned)d < (unsigned)n)
                red_add_v4_f16x2(at + d, __ldg(&ht[s]));
        }
    }
}

// ---- K6: unpack fp16 acc, apply dinv, +b2, log_softmax ---------------------
__global__ void k_out(const float* __restrict__ b2, float* __restrict__ out, int n) {
    int i = blockIdx.x * blockDim.x + threadIdx.x;
    if (i >= n) return;
    float di = g_dinv[i];
    uint4 m = ((const uint4*)g_acc2h)[i];
    __half2 h0 = *(__half2*)&m.x, h1 = *(__half2*)&m.y;
    __half2 h2 = *(__half2*)&m.z, h3 = *(__half2*)&m.w;
    float2 f0 = __half22float2(h0), f1 = __half22float2(h1);
    float2 f2 = __half22float2(h2), f3 = __half22float2(h3);
    float v[F2] = { f0.x, f0.y, f1.x, f1.y, f2.x, f2.y, f3.x };
    float mx = -1e30f;
    #pragma unroll
    for (int j = 0; j < F2; j++) {
        v[j] = di * v[j] + __ldg(&b2[j]);
        mx = fmaxf(mx, v[j]);
    }
    float sum = 0.0f;
    #pragma unroll
    for (int j = 0; j < F2; j++) sum += __expf(v[j] - mx);
    float lse = mx + __logf(sum);
    #pragma unroll
    for (int j = 0; j < F2; j++) out[(size_t)i * F2 + j] = v[j] - lse;
}

// ---------------------------------------------------------------------------
extern "C" void kernel_launch(void* const* d_in, const int* in_sizes, int n_in,
                              void* d_out, int out_size) {
    const float* x  = (const float*)d_in[0];
    const void*  ei = d_in[1];                 // [2, E] dtype detected at runtime
    const float* W1 = (const float*)d_in[2];
    const float* b1 = (const float*)d_in[3];
    const float* W2 = (const float*)d_in[4];
    const float* b2 = (const float*)d_in[5];
    float*       out = (float*)d_out;

    const int n = in_sizes[0] / 3;
    const int e = in_sizes[1] / 2;

    const int BT = 256;
    const int nb_n  = (n + BT - 1) / BT;
    const int nb_e2 = (e / 2 + BT) / BT;   // 2 edges per thread

    k_detect  <<<1, 32>>>(ei, e, n);
    k_zero_deg<<<nb_n,  BT>>>(n);
    k_degree  <<<nb_e2, BT>>>(ei, e, n);
    k_node1   <<<nb_n,  BT>>>(x, n);
    k_edge1   <<<nb_e2, BT>>>(ei, e, n);
    k_node2   <<<nb_n,  BT>>>(W1, b1, W2, n);
    k_edge2   <<<nb_e2, BT>>>(ei, e, n);
    k_out     <<<nb_n,  BT>>>(b2, out, n);
}

// round 16
// speedup vs baseline: 3.9947x; 1.0028x over previous
#include <cuda_runtime.h>
#include <cuda_fp16.h>
#include <cuda_bf16.h>
#include <cstdint>

// ---------------------------------------------------------------------------
// GCN 2-layer forward. N=500000, E=16e6.
// At the 3-red-sweep structural floor (deg, L1 agg, L2 agg). fp16 packed
// messages + hardware vector reductions:
//   g_x4h[i]  = fp16x4( dinv_i * (x_i, 0) )      8B message
//   a1h[d]   += g_x4h[s]   ONE red.v2.f16x2 per edge
//   h[i]      = relu( (dinv_i * a1h[i]) @ W1 + b1 )
//   hw2h[i]   = fp16x8( dinv_i * (h[i] @ W2) )   16B message (7 used)
//   acc2h[d] += hw2h[s]    ONE red.v4.f16x2 per edge
//   out       = log_softmax(dinv_i*acc2h + b2)
// Index loads: vectorized + streaming (.cs) on BOTH dtype paths so the 320MB
// edge stream doesn't evict the hot gather tables from L2.
// ---------------------------------------------------------------------------

#define NMAX 500000
#define F1   16
#define F2   7

__device__ __align__(16) int      g_deg  [NMAX];
__device__ __align__(16) float    g_dinv [NMAX];
__device__ __align__(16) __half   g_x4h  [(size_t)NMAX * 4];   // fp16 L1 messages
__device__ __align__(16) __half   g_a1h  [(size_t)NMAX * 4];   // fp16 L1 accumulator
__device__ __align__(16) __half   g_hw2h [(size_t)NMAX * 8];   // fp16 L2 messages
__device__ __align__(16) __half   g_acc2h[(size_t)NMAX * 8];   // fp16 L2 accumulator
__device__ int g_is64;

// 8B fp16 vector reduction: 4 halves in 2 f16x2 words
__device__ __forceinline__ void red_add_v2_f16x2(void* addr, uint2 m) {
    asm volatile("red.global.add.noftz.v2.f16x2 [%0], {%1, %2};"
                 :: "l"(addr), "r"(m.x), "r"(m.y)
                 : "memory");
}

// 16B fp16 vector reduction: 8 halves in 4 f16x2 words
__device__ __forceinline__ void red_add_v4_f16x2(void* addr, uint4 m) {
    asm volatile("red.global.add.noftz.v4.f16x2 [%0], {%1, %2, %3, %4};"
                 :: "l"(addr), "r"(m.x), "r"(m.y), "r"(m.z), "r"(m.w)
                 : "memory");
}

// streaming 16B load of two int64 indices
__device__ __forceinline__ longlong2 ldcs_ll2(const long long* p) {
    longlong2 r;
    asm volatile("ld.global.cs.v2.s64 {%0, %1}, [%2];"
                 : "=l"(r.x), "=l"(r.y) : "l"(p));
    return r;
}

// streaming 8B load of two int32 indices
__device__ __forceinline__ int2 ldcs_i2(const int* p) {
    int2 r;
    asm volatile("ld.global.cs.v2.s32 {%0, %1}, [%2];"
                 : "=r"(r.x), "=r"(r.y) : "l"(p));
    return r;
}

// ---- K0: detect edge_index dtype + zero degree (merged) --------------------
__global__ void k_detect_zero(const void* ei, int e, int n) {
    int i = blockIdx.x * blockDim.x + threadIdx.x;
    if (i < n) g_deg[i] = 0;
    if (blockIdx.x == 0 && threadIdx.x == 0) {
        const long long* p = (const long long*)ei;
        int ok = 1;
        int step = e / 64;
        if (step < 1) step = 1;
        for (int k = 0; k < 64; k++) {
            size_t idx = (size_t)k * step;
            if (idx * 8 + 8 > (size_t)e * 8) break;
            long long v = p[idx];
            if (v < 0 || v >= n) { ok = 0; break; }
        }
        g_is64 = ok;
    }
}

// ---- K1: in-degree count (dst half only, 2 edges/thread) -------------------
__global__ void k_degree(const void* __restrict__ ei, int e, int n) {
    int t = blockIdx.x * blockDim.x + threadIdx.x;
    int i = t * 2;
    if (i >= e) return;
    if (g_is64) {
        const long long* dstp = (const long long*)ei + e;
        if (i + 1 < e) {
            longlong2 dv = ldcs_ll2(dstp + i);
            if (dv.x >= 0 && dv.x < n) atomicAdd(&g_deg[(int)dv.x], 1);
            if (dv.y >= 0 && dv.y < n) atomicAdd(&g_deg[(int)dv.y], 1);
        } else {
            long long dv = __ldg(dstp + i);
            if (dv >= 0 && dv < n) atomicAdd(&g_deg[(int)dv], 1);
        }
    } else {
        const int* dstp = (const int*)ei + e;
        if (i + 1 < e) {
            int2 d2 = ldcs_i2(dstp + i);
            if ((unsigned)d2.x < (unsigned)n) atomicAdd(&g_deg[d2.x], 1);
            if ((unsigned)d2.y < (unsigned)n) atomicAdd(&g_deg[d2.y], 1);
        } else {
            int d = __ldg(dstp + i);
            if ((unsigned)d < (unsigned)n) atomicAdd(&g_deg[d], 1);
        }
    }
}

// ---- K2: dinv, fp16-packed scaled x + a1 init ------------------------------
__global__ void k_node1(const float* __restrict__ x, int n) {
    int i = blockIdx.x * blockDim.x + threadIdx.x;
    if (i >= n) return;
    float di = rsqrtf((float)(g_deg[i] + 1));
    g_dinv[i] = di;
    __half2 p0 = __floats2half2_rn(di * __ldg(&x[3*i+0]), di * __ldg(&x[3*i+1]));
    __half2 p1 = __floats2half2_rn(di * __ldg(&x[3*i+2]), 0.0f);
    uint2 m;
    m.x = *(uint32_t*)&p0;
    m.y = *(uint32_t*)&p1;
    ((uint2*)g_x4h)[i] = m;
    ((uint2*)g_a1h)[i] = m;   // accumulator init = self-loop term
}

// ---- K3: layer-1 edge scatter — ONE red.v2.f16x2 per edge ------------------
__global__ void k_edge1(const void* __restrict__ ei, int e, int n) {
    int t = blockIdx.x * blockDim.x + threadIdx.x;
    int i = t * 2;
    if (i >= e) return;
    const uint2* xt = (const uint2*)g_x4h;
    uint2*       at = (uint2*)g_a1h;
    if (g_is64) {
        const long long* srcp = (const long long*)ei;
        const long long* dstp = srcp + e;
        if (i + 1 < e) {
            longlong2 sv = ldcs_ll2(srcp + i);
            longlong2 dv = ldcs_ll2(dstp + i);
            if (sv.x >= 0 && sv.x < n && dv.x >= 0 && dv.x < n)
                red_add_v2_f16x2(at + (int)dv.x, __ldg(&xt[(int)sv.x]));
            if (sv.y >= 0 && sv.y < n && dv.y >= 0 && dv.y < n)
                red_add_v2_f16x2(at + (int)dv.y, __ldg(&xt[(int)sv.y]));
        } else {
            long long sv = __ldg(srcp + i), dv = __ldg(dstp + i);
            if (sv >= 0 && sv < n && dv >= 0 && dv < n)
                red_add_v2_f16x2(at + (int)dv, __ldg(&xt[(int)sv]));
        }
    } else {
        const int* srcp = (const int*)ei;
        const int* dstp = srcp + e;
        if (i + 1 < e) {
            int2 s2 = ldcs_i2(srcp + i);
            int2 d2 = ldcs_i2(dstp + i);
            if ((unsigned)s2.x < (unsigned)n && (unsigned)d2.x < (unsigned)n)
                red_add_v2_f16x2(at + d2.x, __ldg(&xt[s2.x]));
            if ((unsigned)s2.y < (unsigned)n && (unsigned)d2.y < (unsigned)n)
                red_add_v2_f16x2(at + d2.y, __ldg(&xt[s2.y]));
        } else {
            int s = __ldg(srcp + i), d = __ldg(dstp + i);
            if ((unsigned)s < (unsigned)n && (unsigned)d < (unsigned)n)
                red_add_v2_f16x2(at + d, __ldg(&xt[s]));
        }
    }
}

// ---- K4: finish layer 1, build fp16-packed scaled hW2 ----------------------
__global__ void k_node2(const float* __restrict__ W1,
                        const float* __restrict__ b1,
                        const float* __restrict__ W2, int n) {
    int i = blockIdx.x * blockDim.x + threadIdx.x;
    if (i >= n) return;
    float di = g_dinv[i];
    uint2 am = ((const uint2*)g_a1h)[i];
    __half2 a01 = *(__half2*)&am.x, a23 = *(__half2*)&am.y;
    float2 f01 = __half22float2(a01), f23 = __half22float2(a23);
    float a0 = di * f01.x, a1v = di * f01.y, a2 = di * f23.x;
    float h[F1];
    #pragma unroll
    for (int j = 0; j < F1; j++)
        h[j] = fmaxf(a0 * __ldg(&W1[j]) + a1v * __ldg(&W1[F1 + j])
                   + a2 * __ldg(&W1[2*F1 + j]) + __ldg(&b1[j]), 0.0f);
    float v[8];
    #pragma unroll
    for (int j = 0; j < F2; j++) {
        float acc = 0.0f;
        #pragma unroll
        for (int k = 0; k < F1; k++)
            acc += h[k] * __ldg(&W2[k * F2 + j]);
        v[j] = di * acc;
    }
    v[F2] = 0.0f;
    __half2 p0 = __floats2half2_rn(v[0], v[1]);
    __half2 p1 = __floats2half2_rn(v[2], v[3]);
    __half2 p2 = __floats2half2_rn(v[4], v[5]);
    __half2 p3 = __floats2half2_rn(v[6], v[7]);
    uint4 m;
    m.x = *(uint32_t*)&p0; m.y = *(uint32_t*)&p1;
    m.z = *(uint32_t*)&p2; m.w = *(uint32_t*)&p3;
    ((uint4*)g_hw2h)[i]  = m;
    ((uint4*)g_acc2h)[i] = m;   // accumulator init = self-loop term
}

// ---- K5: layer-2 edge scatter — ONE red.v4.f16x2 per edge ------------------
__global__ void k_edge2(const void* __restrict__ ei, int e, int n) {
    int t = blockIdx.x * blockDim.x + threadIdx.x;
    int i = t * 2;
    if (i >= e) return;
    const uint4* ht = (const uint4*)g_hw2h;
    uint4*       at = (uint4*)g_acc2h;
    if (g_is64) {
        const long long* srcp = (const long long*)ei;
        const long long* dstp = srcp + e;
        if (i + 1 < e) {
            longlong2 sv = ldcs_ll2(srcp + i);
            longlong2 dv = ldcs_ll2(dstp + i);
            if (sv.x >= 0 && sv.x < n && dv.x >= 0 && dv.x < n)
                red_add_v4_f16x2(at + (int)dv.x, __ldg(&ht[(int)sv.x]));
            if (sv.y >= 0 && sv.y < n && dv.y >= 0 && dv.y < n)
                red_add_v4_f16x2(at + (int)dv.y, __ldg(&ht[(int)sv.y]));
        } else {
            long long sv = __ldg(srcp + i), dv = __ldg(dstp + i);
            if (sv >= 0 && sv < n && dv >= 0 && dv < n)
                red_add_v4_f16x2(at + (int)dv, __ldg(&ht[(int)sv]));
        }
    } else {
        const int* srcp = (const int*)ei;
        const int* dstp = srcp + e;
        if (i + 1 < e) {
            int2 s2 = ldcs_i2(srcp + i);
            int2 d2 = ldcs_i2(dstp + i);
            if ((unsigned)s2.x < (unsigned)n && (unsigned)d2.x < (unsigned)n)
                red_add_v4_f16x2(at + d2.x, __ldg(&ht[s2.x]));
            if ((unsigned)s2.y < (unsigned)n && (unsigned)d2.y < (unsigned)n)
                red_add_v4_f16x2(at + d2.y, __ldg(&ht[s2.y]));
        } else {
            int s = __ldg(srcp + i), d = __ldg(dstp + i);
            if ((unsigned)s < (unsigned)n && (unsigned)d < (unsigned)n)
                red_add_v4_f16x2(at + d, __ldg(&ht[s]));
        }
    }
}

// ---- K6: unpack fp16 acc, apply dinv, +b2, log_softmax ---------------------
__global__ void k_out(const float* __restrict__ b2, float* __restrict__ out, int n) {
    int i = blockIdx.x * blockDim.x + threadIdx.x;
    if (i >= n) return;
    float di = g_dinv[i];
    uint4 m = ((const uint4*)g_acc2h)[i];
    __half2 h0 = *(__half2*)&m.x, h1 = *(__half2*)&m.y;
    __half2 h2 = *(__half2*)&m.z, h3 = *(__half2*)&m.w;
    float2 f0 = __half22float2(h0), f1 = __half22float2(h1);
    float2 f2 = __half22float2(h2), f3 = __half22float2(h3);
    float v[F2] = { f0.x, f0.y, f1.x, f1.y, f2.x, f2.y, f3.x };
    float mx = -1e30f;
    #pragma unroll
    for (int j = 0; j < F2; j++) {
        v[j] = di * v[j] + __ldg(&b2[j]);
        mx = fmaxf(mx, v[j]);
    }
    float sum = 0.0f;
    #pragma unroll
    for (int j = 0; j < F2; j++) sum += __expf(v[j] - mx);
    float lse = mx + __logf(sum);
    #pragma unroll
    for (int j = 0; j < F2; j++) out[(size_t)i * F2 + j] = v[j] - lse;
}

// ---------------------------------------------------------------------------
extern "C" void kernel_launch(void* const* d_in, const int* in_sizes, int n_in,
                              void* d_out, int out_size) {
    const float* x  = (const float*)d_in[0];
    const void*  ei = d_in[1];                 // [2, E] dtype detected at runtime
    const float* W1 = (const float*)d_in[2];
    const float* b1 = (const float*)d_in[3];
    const float* W2 = (const float*)d_in[4];
    const float* b2 = (const float*)d_in[5];
    float*       out = (float*)d_out;

    const int n = in_sizes[0] / 3;
    const int e = in_sizes[1] / 2;

    const int BT = 256;
    const int nb_n  = (n + BT - 1) / BT;
    const int nb_e2 = (e / 2 + BT) / BT;   // 2 edges per thread

    k_detect_zero<<<nb_n,  BT>>>(ei, e, n);
    k_degree     <<<nb_e2, BT>>>(ei, e, n);
    k_node1      <<<nb_n,  BT>>>(x, n);
    k_edge1      <<<nb_e2, BT>>>(ei, e, n);
    k_node2      <<<nb_n,  BT>>>(W1, b1, W2, n);
    k_edge2      <<<nb_e2, BT>>>(ei, e, n);
    k_out        <<<nb_n,  BT>>>(b2, out, n);
}

// round 17
// speedup vs baseline: 4.0052x; 1.0026x over previous
#include <cuda_runtime.h>
#include <cuda_fp16.h>
#include <cuda_bf16.h>
#include <cstdint>

// ---------------------------------------------------------------------------
// GCN 2-layer forward. N=500000, E=16e6.
// 3 red-sweeps (structural floor): degree, layer-1 agg, layer-2 agg.
// fp16 packed messages + hardware vector reductions.
// This round: message gathers use ld.global.cg (L2-only, no L1 allocation) —
// profile showed L1tex at 83.4% from useless L1 fills on random gathers.
// ---------------------------------------------------------------------------

#define NMAX 500000
#define F1   16
#define F2   7

__device__ __align__(16) int      g_deg  [NMAX];
__device__ __align__(16) float    g_dinv [NMAX];
__device__ __align__(16) __half   g_x4h  [(size_t)NMAX * 4];   // fp16 L1 messages
__device__ __align__(16) __half   g_a1h  [(size_t)NMAX * 4];   // fp16 L1 accumulator
__device__ __align__(16) __half   g_hw2h [(size_t)NMAX * 8];   // fp16 L2 messages
__device__ __align__(16) __half   g_acc2h[(size_t)NMAX * 8];   // fp16 L2 accumulator
__device__ int g_is64;

// 8B fp16 vector reduction: 4 halves in 2 f16x2 words
__device__ __forceinline__ void red_add_v2_f16x2(void* addr, uint2 m) {
    asm volatile("red.global.add.noftz.v2.f16x2 [%0], {%1, %2};"
                 :: "l"(addr), "r"(m.x), "r"(m.y)
                 : "memory");
}

// 16B fp16 vector reduction: 8 halves in 4 f16x2 words
__device__ __forceinline__ void red_add_v4_f16x2(void* addr, uint4 m) {
    asm volatile("red.global.add.noftz.v4.f16x2 [%0], {%1, %2, %3, %4};"
                 :: "l"(addr), "r"(m.x), "r"(m.y), "r"(m.z), "r"(m.w)
                 : "memory");
}

// L2-only (no L1 allocation) 8B gather
__device__ __forceinline__ uint2 ldcg_u2(const uint2* p) {
    uint2 r;
    asm volatile("ld.global.cg.v2.b32 {%0, %1}, [%2];"
                 : "=r"(r.x), "=r"(r.y) : "l"(p));
    return r;
}

// L2-only (no L1 allocation) 16B gather
__device__ __forceinline__ uint4 ldcg_u4(const uint4* p) {
    uint4 r;
    asm volatile("ld.global.cg.v4.b32 {%0, %1, %2, %3}, [%4];"
                 : "=r"(r.x), "=r"(r.y), "=r"(r.z), "=r"(r.w) : "l"(p));
    return r;
}

// streaming 16B load of two int64 indices
__device__ __forceinline__ longlong2 ldcs_ll2(const long long* p) {
    longlong2 r;
    asm volatile("ld.global.cs.v2.s64 {%0, %1}, [%2];"
                 : "=l"(r.x), "=l"(r.y) : "l"(p));
    return r;
}

// streaming 8B load of two int32 indices
__device__ __forceinline__ int2 ldcs_i2(const int* p) {
    int2 r;
    asm volatile("ld.global.cs.v2.s32 {%0, %1}, [%2];"
                 : "=r"(r.x), "=r"(r.y) : "l"(p));
    return r;
}

// ---- K0: detect edge_index dtype + zero degree (merged) --------------------
__global__ void k_detect_zero(const void* ei, int e, int n) {
    int i = blockIdx.x * blockDim.x + threadIdx.x;
    if (i < n) g_deg[i] = 0;
    if (blockIdx.x == 0 && threadIdx.x == 0) {
        const long long* p = (const long long*)ei;
        int ok = 1;
        int step = e / 64;
        if (step < 1) step = 1;
        for (int k = 0; k < 64; k++) {
            size_t idx = (size_t)k * step;
            if (idx * 8 + 8 > (size_t)e * 8) break;
            long long v = p[idx];
            if (v < 0 || v >= n) { ok = 0; break; }
        }
        g_is64 = ok;
    }
}

// ---- K1: in-degree count (dst half only, 2 edges/thread) -------------------
__global__ void k_degree(const void* __restrict__ ei, int e, int n) {
    int t = blockIdx.x * blockDim.x + threadIdx.x;
    int i = t * 2;
    if (i >= e) return;
    if (g_is64) {
        const long long* dstp = (const long long*)ei + e;
        if (i + 1 < e) {
            longlong2 dv = ldcs_ll2(dstp + i);
            if (dv.x >= 0 && dv.x < n) atomicAdd(&g_deg[(int)dv.x], 1);
            if (dv.y >= 0 && dv.y < n) atomicAdd(&g_deg[(int)dv.y], 1);
        } else {
            long long dv = __ldg(dstp + i);
            if (dv >= 0 && dv < n) atomicAdd(&g_deg[(int)dv], 1);
        }
    } else {
        const int* dstp = (const int*)ei + e;
        if (i + 1 < e) {
            int2 d2 = ldcs_i2(dstp + i);
            if ((unsigned)d2.x < (unsigned)n) atomicAdd(&g_deg[d2.x], 1);
            if ((unsigned)d2.y < (unsigned)n) atomicAdd(&g_deg[d2.y], 1);
        } else {
            int d = __ldg(dstp + i);
            if ((unsigned)d < (unsigned)n) atomicAdd(&g_deg[d], 1);
        }
    }
}

// ---- K2: dinv, fp16-packed scaled x + a1 init ------------------------------
__global__ void k_node1(const float* __restrict__ x, int n) {
    int i = blockIdx.x * blockDim.x + threadIdx.x;
    if (i >= n) return;
    float di = rsqrtf((float)(g_deg[i] + 1));
    g_dinv[i] = di;
    __half2 p0 = __floats2half2_rn(di * __ldg(&x[3*i+0]), di * __ldg(&x[3*i+1]));
    __half2 p1 = __floats2half2_rn(di * __ldg(&x[3*i+2]), 0.0f);
    uint2 m;
    m.x = *(uint32_t*)&p0;
    m.y = *(uint32_t*)&p1;
    ((uint2*)g_x4h)[i] = m;
    ((uint2*)g_a1h)[i] = m;   // accumulator init = self-loop term
}

// ---- K3: layer-1 edge scatter — 1 cg-gather + 1 red.v2.f16x2 per edge ------
__global__ void k_edge1(const void* __restrict__ ei, int e, int n) {
    int t = blockIdx.x * blockDim.x + threadIdx.x;
    int i = t * 2;
    if (i >= e) return;
    const uint2* xt = (const uint2*)g_x4h;
    uint2*       at = (uint2*)g_a1h;
    if (g_is64) {
        const long long* srcp = (const long long*)ei;
        const long long* dstp = srcp + e;
        if (i + 1 < e) {
            longlong2 sv = ldcs_ll2(srcp + i);
            longlong2 dv = ldcs_ll2(dstp + i);
            if (sv.x >= 0 && sv.x < n && dv.x >= 0 && dv.x < n)
                red_add_v2_f16x2(at + (int)dv.x, ldcg_u2(&xt[(int)sv.x]));
            if (sv.y >= 0 && sv.y < n && dv.y >= 0 && dv.y < n)
                red_add_v2_f16x2(at + (int)dv.y, ldcg_u2(&xt[(int)sv.y]));
        } else {
            long long sv = __ldg(srcp + i), dv = __ldg(dstp + i);
            if (sv >= 0 && sv < n && dv >= 0 && dv < n)
                red_add_v2_f16x2(at + (int)dv, ldcg_u2(&xt[(int)sv]));
        }
    } else {
        const int* srcp = (const int*)ei;
        const int* dstp = srcp + e;
        if (i + 1 < e) {
            int2 s2 = ldcs_i2(srcp + i);
            int2 d2 = ldcs_i2(dstp + i);
            if ((unsigned)s2.x < (unsigned)n && (unsigned)d2.x < (unsigned)n)
                red_add_v2_f16x2(at + d2.x, ldcg_u2(&xt[s2.x]));
            if ((unsigned)s2.y < (unsigned)n && (unsigned)d2.y < (unsigned)n)
                red_add_v2_f16x2(at + d2.y, ldcg_u2(&xt[s2.y]));
        } else {
            int s = __ldg(srcp + i), d = __ldg(dstp + i);
            if ((unsigned)s < (unsigned)n && (unsigned)d < (unsigned)n)
                red_add_v2_f16x2(at + d, ldcg_u2(&xt[s]));
        }
    }
}

// ---- K4: finish layer 1, build fp16-packed scaled hW2 ----------------------
__global__ void k_node2(const float* __restrict__ W1,
                        const float* __restrict__ b1,
                        const float* __restrict__ W2, int n) {
    int i = blockIdx.x * blockDim.x + threadIdx.x;
    if (i >= n) return;
    float di = g_dinv[i];
    uint2 am = ((const uint2*)g_a1h)[i];
    __half2 a01 = *(__half2*)&am.x, a23 = *(__half2*)&am.y;
    float2 f01 = __half22float2(a01), f23 = __half22float2(a23);
    float a0 = di * f01.x, a1v = di * f01.y, a2 = di * f23.x;
    float h[F1];
    #pragma unroll
    for (int j = 0; j < F1; j++)
        h[j] = fmaxf(a0 * __ldg(&W1[j]) + a1v * __ldg(&W1[F1 + j])
                   + a2 * __ldg(&W1[2*F1 + j]) + __ldg(&b1[j]), 0.0f);
    float v[8];
    #pragma unroll
    for (int j = 0; j < F2; j++) {
        float acc = 0.0f;
        #pragma unroll
        for (int k = 0; k < F1; k++)
            acc += h[k] * __ldg(&W2[k * F2 + j]);
        v[j] = di * acc;
    }
    v[F2] = 0.0f;
    __half2 p0 = __floats2half2_rn(v[0], v[1]);
    __half2 p1 = __floats2half2_rn(v[2], v[3]);
    __half2 p2 = __floats2half2_rn(v[4], v[5]);
    __half2 p3 = __floats2half2_rn(v[6], v[7]);
    uint4 m;
    m.x = *(uint32_t*)&p0; m.y = *(uint32_t*)&p1;
    m.z = *(uint32_t*)&p2; m.w = *(uint32_t*)&p3;
    ((uint4*)g_hw2h)[i]  = m;
    ((uint4*)g_acc2h)[i] = m;   // accumulator init = self-loop term
}

// ---- K5: layer-2 edge scatter — 1 cg-gather + 1 red.v4.f16x2 per edge ------
__global__ void k_edge2(const void* __restrict__ ei, int e, int n) {
    int t = blockIdx.x * blockDim.x + threadIdx.x;
    int i = t * 2;
    if (i >= e) return;
    const uint4* ht = (const uint4*)g_hw2h;
    uint4*       at = (uint4*)g_acc2h;
    if (g_is64) {
        const long long* srcp = (const long long*)ei;
        const long long* dstp = srcp + e;
        if (i + 1 < e) {
            longlong2 sv = ldcs_ll2(srcp + i);
            longlong2 dv = ldcs_ll2(dstp + i);
            if (sv.x >= 0 && sv.x < n && dv.x >= 0 && dv.x < n)
                red_add_v4_f16x2(at + (int)dv.x, ldcg_u4(&ht[(int)sv.x]));
            if (sv.y >= 0 && sv.y < n && dv.y >= 0 && dv.y < n)
                red_add_v4_f16x2(at + (int)dv.y, ldcg_u4(&ht[(int)sv.y]));
        } else {
            long long sv = __ldg(srcp + i), dv = __ldg(dstp + i);
            if (sv >= 0 && sv < n && dv >= 0 && dv < n)
                red_add_v4_f16x2(at + (int)dv, ldcg_u4(&ht[(int)sv]));
        }
    } else {
        const int* srcp = (const int*)ei;
        const int* dstp = srcp + e;
        if (i + 1 < e) {
            int2 s2 = ldcs_i2(srcp + i);
            int2 d2 = ldcs_i2(dstp + i);
            if ((unsigned)s2.x < (unsigned)n && (unsigned)d2.x < (unsigned)n)
                red_add_v4_f16x2(at + d2.x, ldcg_u4(&ht[s2.x]));
            if ((unsigned)s2.y < (unsigned)n && (unsigned)d2.y < (unsigned)n)
                red_add_v4_f16x2(at + d2.y, ldcg_u4(&ht[s2.y]));
        } else {
            int s = __ldg(srcp + i), d = __ldg(dstp + i);
            if ((unsigned)s < (unsigned)n && (unsigned)d < (unsigned)n)
                red_add_v4_f16x2(at + d, ldcg_u4(&ht[s]));
        }
    }
}

// ---- K6: unpack fp16 acc, apply dinv, +b2, log_softmax ---------------------
__global__ void k_out(const float* __restrict__ b2, float* __restrict__ out, int n) {
    int i = blockIdx.x * blockDim.x + threadIdx.x;
    if (i >= n) return;
    float di = g_dinv[i];
    uint4 m = ((const uint4*)g_acc2h)[i];
    __half2 h0 = *(__half2*)&m.x, h1 = *(__half2*)&m.y;
    __half2 h2 = *(__half2*)&m.z, h3 = *(__half2*)&m.w;
    float2 f0 = __half22float2(h0), f1 = __half22float2(h1);
    float2 f2 = __half22float2(h2), f3 = __half22float2(h3);
    float v[F2] = { f0.x, f0.y, f1.x, f1.y, f2.x, f2.y, f3.x };
    float mx = -1e30f;
    #pragma unroll
    for (int j = 0; j < F2; j++) {
        v[j] = di * v[j] + __ldg(&b2[j]);
        mx = fmaxf(mx, v[j]);
    }
    float sum = 0.0f;
    #pragma unroll
    for (int j = 0; j < F2; j++) sum += __expf(v[j] - mx);
    float lse = mx + __logf(sum);
    #pragma unroll
    for (int j = 0; j < F2; j++) out[(size_t)i * F2 + j] = v[j] - lse;
}

// ---------------------------------------------------------------------------
extern "C" void kernel_launch(void* const* d_in, const int* in_sizes, int n_in,
                              void* d_out, int out_size) {
    const float* x  = (const float*)d_in[0];
    const void*  ei = d_in[1];                 // [2, E] dtype detected at runtime
    const float* W1 = (const float*)d_in[2];
    const float* b1 = (const float*)d_in[3];
    const float* W2 = (const float*)d_in[4];
    const float* b2 = (const float*)d_in[5];
    float*       out = (float*)d_out;

    const int n = in_sizes[0] / 3;
    const int e = in_sizes[1] / 2;

    const int BT = 256;
    const int nb_n  = (n + BT - 1) / BT;
    const int nb_e2 = (e / 2 + BT) / BT;   // 2 edges per thread

    k_detect_zero<<<nb_n,  BT>>>(ei, e, n);
    k_degree     <<<nb_e2, BT>>>(ei, e, n);
    k_node1      <<<nb_n,  BT>>>(x, n);
    k_edge1      <<<nb_e2, BT>>>(ei, e, n);
    k_node2      <<<nb_n,  BT>>>(W1, b1, W2, n);
    k_edge2      <<<nb_e2, BT>>>(ei, e, n);
    k_out        <<<nb_n,  BT>>>(b2, out, n);
}